// round 3
// baseline (speedup 1.0000x reference)
#include <cuda_runtime.h>
#include <math.h>

#define NN 80
#define PAIRS (NN * NN)          // 6400
#define MAX_ITERS 60
#define TOL 1e-3f
#define TPB 256

__global__ void zero_out(float* __restrict__ out) {
    out[threadIdx.x] = 0.0f;     // d_out is poisoned; we accumulate atomically
}

__global__ __launch_bounds__(TPB, 4)
void power_iter_kernel(const float* __restrict__ r_zeros,
                       const float* __restrict__ r_const,
                       const float* __restrict__ t_paths,
                       const float* __restrict__ weights_t,
                       const float* __restrict__ weights_r,
                       float* __restrict__ out) {
    __shared__ __align__(16) float v[NN];   // current eigenvector estimate
    __shared__ float wv[NN];                 // w = A v
    __shared__ float red_ww[8];              // per-warp partials of w.w
    __shared__ float red_vw[8];              // per-warp partials of v.w
    __shared__ float s_n2;                   // broadcast ||w||^2
    __shared__ float s_ev;                   // broadcast v.(Av)

    const int p    = blockIdx.x;
    const int tid  = threadIdx.x;
    const int warp = tid >> 5;
    const int lane = tid & 31;
    const int half = lane >> 4;              // 0/1: which row of the pair
    const int c    = lane & 15;              // column-group within row

    // ---- Build A = weights_r * r_zeros + r_const into registers.
    // Warp w, group k owns rows {2w+16k, 2w+16k+1}. Lane holds cols
    // {4c,4c+1,4c+2,4c+3} (float4) and tail col 64+c. Rows 0..79 covered.
    const size_t base = (size_t)p * (NN * NN);
    const float* __restrict__ rz = r_zeros   + base;
    const float* __restrict__ rc = r_const   + base;
    const float* __restrict__ wr = weights_r + base;

    float4 A4[5];
    float  A1[5];
    #pragma unroll
    for (int k = 0; k < 5; ++k) {
        const int row = (warp << 1) + (k << 4) + half;
        const int o4  = row * NN + (c << 2);         // 16B-aligned
        const float4 a = __ldcs((const float4*)(wr + o4));
        const float4 b = __ldcs((const float4*)(rz + o4));
        const float4 d = __ldcs((const float4*)(rc + o4));
        A4[k].x = fmaf(a.x, b.x, d.x);
        A4[k].y = fmaf(a.y, b.y, d.y);
        A4[k].z = fmaf(a.z, b.z, d.z);
        A4[k].w = fmaf(a.w, b.w, d.w);
        const int ot = row * NN + 64 + c;
        A1[k] = fmaf(__ldcs(wr + ot), __ldcs(rz + ot), __ldcs(rc + ot));
    }

    if (tid < NN) v[tid] = 0.11180339887498949f;  // 1/sqrt(80)
    __syncthreads();

    // Fused matvec + dots: wv = A v ; s_n2 = wv.wv ; s_ev = v.wv
    auto mv = [&]() {
        const float4 v4 = ((const float4*)v)[c];
        const float  vt = v[64 + c];
        float ww = 0.0f, vwacc = 0.0f;
        #pragma unroll
        for (int k = 0; k < 5; ++k) {
            float s = A4[k].x * v4.x;
            s = fmaf(A4[k].y, v4.y, s);
            s = fmaf(A4[k].z, v4.z, s);
            s = fmaf(A4[k].w, v4.w, s);
            s = fmaf(A1[k],   vt,   s);
            // reduce over the 16 lanes of this half-warp
            s += __shfl_xor_sync(0xFFFFFFFFu, s, 8);
            s += __shfl_xor_sync(0xFFFFFFFFu, s, 4);
            s += __shfl_xor_sync(0xFFFFFFFFu, s, 2);
            s += __shfl_xor_sync(0xFFFFFFFFu, s, 1);
            if (c == 0) {
                const int row = (warp << 1) + (k << 4) + half;
                wv[row] = s;
                ww    = fmaf(s, s, ww);
                vwacc = fmaf(v[row], s, vwacc);
            }
        }
        // combine the two half-warp accumulators (lanes 0 and 16 hold data)
        ww    += __shfl_xor_sync(0xFFFFFFFFu, ww,    16);
        vwacc += __shfl_xor_sync(0xFFFFFFFFu, vwacc, 16);
        if (lane == 0) { red_ww[warp] = ww; red_vw[warp] = vwacc; }
        __syncthreads();
        if (tid == 0) {
            float sa = 0.0f, sb = 0.0f;
            #pragma unroll
            for (int k = 0; k < 8; ++k) { sa += red_ww[k]; sb += red_vw[k]; }
            s_n2 = sa; s_ev = sb;
        }
        __syncthreads();
    };

    // ---- ev0 = v0 . (A v0)
    mv();
    float ev = s_ev;

    // ---- scan body x60 with convergence break (v updated on converging step)
    for (int it = 0; it < MAX_ITERS; ++it) {
        const float inv = 1.0f / sqrtf(s_n2);
        if (tid < NN) v[tid] = wv[tid] * inv;     // v_new = Av / ||Av||
        __syncthreads();
        mv();                                      // wv = A v_new ; s_ev = v_new.wv
        const float ev_new = s_ev;
        if (fabsf(ev - ev_new) < TOL) break;       // uniform branch
        ev = ev_new;
    }

    // ---- out[i] += v[i] * (T[p] / v[src]),  src = p / n  (atomic accumulate)
    if (tid < NN) {
        const float tval = weights_t[p] * t_paths[p];
        const float coef = tval / v[p / NN];
        atomicAdd(&out[tid], v[tid] * coef);
    }
}

extern "C" void kernel_launch(void* const* d_in, const int* in_sizes, int n_in,
                              void* d_out, int out_size) {
    // metadata order: 0:x (unused), 1:r_zeros, 2:r_const, 3:t_paths,
    //                 4:weights_t, 5:weights_r
    const float* r_zeros   = (const float*)d_in[1];
    const float* r_const   = (const float*)d_in[2];
    const float* t_paths   = (const float*)d_in[3];
    const float* weights_t = (const float*)d_in[4];
    const float* weights_r = (const float*)d_in[5];
    float* out = (float*)d_out;

    zero_out<<<1, NN>>>(out);
    power_iter_kernel<<<PAIRS, TPB>>>(r_zeros, r_const, t_paths, weights_t,
                                      weights_r, out);
}